// round 16
// baseline (speedup 1.0000x reference)
#include <cuda_runtime.h>

#define TT    8192
#define NTH   256
#define NW    (NTH/32)
#define FEPS  1e-8f

// ---- ema geometry: SEG=4096, halo 256, merged 3-EMA scan ----
#define SEG1  4096
#define HALO1 256
#define TOT1  (SEG1 + HALO1)       // 4352
#define CHS   17                   // TOT1/NTH
#define SC1   (TOT1 + TOT1/32)     // 4488
#define CH1   16

// ---- win geometry ----
#define WSEG  1024
#define WCH   4

__device__ __forceinline__ int PADI(int i){ return i + (i >> 5); }
__device__ __forceinline__ float sum4(float4 v){ return (v.x + v.y) + (v.z + v.w); }

// ======================= ema body: features 9,10,11 (r15 proven) =======================
__device__ void ema_body(int blk, const float* __restrict__ gclose,
                         float* __restrict__ gout, size_t BT)
{
    __shared__ float sc[SC1];
    __shared__ float swp[3 * NW];
    __shared__ float si[3 * NTH];

    const int row  = blk >> 1;
    const int seg  = blk & 1;
    const int tid  = threadIdx.x;
    const int lane = tid & 31;
    const int wid  = tid >> 5;
    const float* x = gclose + (size_t)row * TT;
    const int basem = seg * SEG1;

    {
        const float x0 = x[0];
        #pragma unroll
        for (int j = 0; j < 5; ++j) {
            int i4 = tid + j * NTH;
            if (i4 < TOT1 / 4) {
                int gi = basem - HALO1 + i4 * 4;
                float4 v = (gi >= 0) ? *(const float4*)(x + gi)
                                     : make_float4(x0, x0, x0, x0);
                int b = i4 * 4;
                sc[PADI(b)]     = v.x;
                sc[PADI(b + 1)] = v.y;
                sc[PADI(b + 2)] = v.z;
                sc[PADI(b + 3)] = v.w;
            }
        }
    }
    __syncthreads();

    const float aF = 2.0f / 13.0f, omF = 1.0f - aF;
    const float aS = 2.0f / 27.0f, omS = 1.0f - aS;
    const float aG = 0.2f,         omG = 0.8f;

    const int i0 = HALO1 + CH1 * tid;

    float cF = 1.f, dF = 0.f, cS = 1.f, dS = 0.f;
    float cG = 1.f, p = 0.f, q = 0.f, d9 = 0.f;
    {
        const int s0 = tid * CHS;
        #pragma unroll
        for (int k = 0; k < CHS; ++k) {
            float v = sc[PADI(s0 + k)];
            dF = fmaf(aF, v, omF * dF); cF *= omF;
            dS = fmaf(aS, v, omS * dS); cS *= omS;
            d9 = fmaf(omG, d9, aG * (dF - dS));
            p  = fmaf(omG, p,  aG * cF);
            q  = fmaf(omG, q, -aG * cS);
            cG *= omG;
        }
    }

    #pragma unroll
    for (int off = 1; off < 32; off <<= 1) {
        float pcF = __shfl_up_sync(0xffffffffu, cF, off);
        float pdF = __shfl_up_sync(0xffffffffu, dF, off);
        float pcS = __shfl_up_sync(0xffffffffu, cS, off);
        float pdS = __shfl_up_sync(0xffffffffu, dS, off);
        float pcG = __shfl_up_sync(0xffffffffu, cG, off);
        float pp  = __shfl_up_sync(0xffffffffu, p,  off);
        float pq  = __shfl_up_sync(0xffffffffu, q,  off);
        float pd9 = __shfl_up_sync(0xffffffffu, d9, off);
        if (lane >= off) {
            float nd9 = fmaf(p, pdF, fmaf(q, pdS, fmaf(cG, pd9, d9)));
            float np  = fmaf(p, pcF, cG * pp);
            float nq  = fmaf(q, pcS, cG * pq);
            dF = fmaf(pdF, cF, dF); cF *= pcF;
            dS = fmaf(pdS, cS, dS); cS *= pcS;
            cG *= pcG;
            p = np; q = nq; d9 = nd9;
        }
    }
    if (lane == 31) { swp[wid] = dF; swp[NW + wid] = dS; swp[2 * NW + wid] = d9; }
    float udF = __shfl_up_sync(0xffffffffu, dF, 1);
    float ucF = __shfl_up_sync(0xffffffffu, cF, 1);
    float udS = __shfl_up_sync(0xffffffffu, dS, 1);
    float ucS = __shfl_up_sync(0xffffffffu, cS, 1);
    float ud9 = __shfl_up_sync(0xffffffffu, d9, 1);
    float up  = __shfl_up_sync(0xffffffffu, p,  1);
    float uq  = __shfl_up_sync(0xffffffffu, q,  1);
    float ucG = __shfl_up_sync(0xffffffffu, cG, 1);
    __syncthreads();
    float bF = (wid > 0) ? swp[wid - 1]          : 0.f;
    float bS = (wid > 0) ? swp[NW + wid - 1]     : 0.f;
    float b9 = (wid > 0) ? swp[2 * NW + wid - 1] : 0.f;

    float yF0, yS0, y90;
    if (lane == 0) { yF0 = bF; yS0 = bS; y90 = b9; }
    else {
        yF0 = fmaf(ucF, bF, udF);
        yS0 = fmaf(ucS, bS, udS);
        y90 = fmaf(up, bF, fmaf(uq, bS, fmaf(ucG, b9, ud9)));
    }
    si[tid] = yF0; si[NTH + tid] = yS0; si[2 * NTH + tid] = y90;
    __syncthreads();

    {
        int c = i0 / CHS;
        int r = i0 - c * CHS;
        float yF = si[c], yS = si[NTH + c], y9 = si[2 * NTH + c];
        int pofs = c * CHS;
        #pragma unroll 1
        for (int k = 0; k < CHS; ++k) {
            if (k >= r) break;
            float vv = sc[PADI(pofs + k)];
            yF = fmaf(aF, vv, omF * yF);
            yS = fmaf(aS, vv, omS * yS);
            float m = yF - yS;
            y9 = fmaf(aG, m, omG * y9);
        }
        float* ob  = gout + (size_t)row * TT + basem + CH1 * tid;
        float* om9 = ob + 9  * BT;
        float* osg = ob + 10 * BT;
        float* oh  = ob + 11 * BT;
        #pragma unroll
        for (int g = 0; g < CH1 / 4; ++g) {
            float mb[4], sb[4], hb[4];
            #pragma unroll
            for (int jj = 0; jj < 4; ++jj) {
                float vv = sc[PADI(i0 + g * 4 + jj)];
                yF = fmaf(aF, vv, omF * yF);
                yS = fmaf(aS, vv, omS * yS);
                float m = yF - yS;
                y9 = fmaf(aG, m, omG * y9);
                mb[jj] = m; sb[jj] = y9; hb[jj] = m - y9;
            }
            __stcs((float4*)(om9 + g * 4), make_float4(mb[0], mb[1], mb[2], mb[3]));
            __stcs((float4*)(osg + g * 4), make_float4(sb[0], sb[1], sb[2], sb[3]));
            __stcs((float4*)(oh  + g * 4), make_float4(hb[0], hb[1], hb[2], hb[3]));
        }
    }
}

// ======== win body: features 0-8, 12-16 — CH=4, reg-dieted (≤51 regs target) ========
__device__ void win_body(int blk, const float* __restrict__ gclose,
                         float* __restrict__ gout, size_t BT)
{
    const int row = blk >> 3;
    const int seg = blk & 7;
    const int tid = threadIdx.x;
    const float* G = gclose + (size_t)row * TT;
    const int gbase = seg * WSEG + WCH * tid;
    float* ob = gout + (size_t)row * TT + gbase;

    if (gbase >= 52) {
        const float* P = G + gbase;

        // --- h-stage: near history stays live, everything else staged ---
        float4 h1 = *(const float4*)(P - 4);
        float4 h2 = *(const float4*)(P - 8);
        float4 h3 = *(const float4*)(P - 12);
        float4 h4 = *(const float4*)(P - 16);
        float4 h5 = *(const float4*)(P - 20);
        float4 xt = *(const float4*)(P);

        float w   = sum4(h1) + sum4(h2) + sum4(h3) + sum4(h4) + sum4(h5);  // -20..-1
        float s10 = h3.z + h3.w + sum4(h2) + sum4(h1);
        float s5  = h2.w + sum4(h1);
        float gs = 0.f, ls = 0.f;
        {
            #define RSTEP(a, b) { float d = (b) - (a); gs += fmaxf(d, 0.f); ls += fmaxf(-d, 0.f); }
            RSTEP(h4.y, h4.z) RSTEP(h4.z, h4.w) RSTEP(h4.w, h3.x)
            RSTEP(h3.x, h3.y) RSTEP(h3.y, h3.z) RSTEP(h3.z, h3.w)
            RSTEP(h3.w, h2.x) RSTEP(h2.x, h2.y) RSTEP(h2.y, h2.z)
            RSTEP(h2.z, h2.w) RSTEP(h2.w, h1.x) RSTEP(h1.x, h1.y)
            RSTEP(h1.y, h1.z) RSTEP(h1.z, h1.w)
            #undef RSTEP
        }
        float xprev = h1.w;
        float xm15  = h4.y;

        // --- wd: r-vectors summed as loaded (die immediately) ---
        float wd;
        {
            float4 r;
            r = *(const float4*)(P - 24); wd  = sum4(r);
            r = *(const float4*)(P - 28); wd += sum4(r);
            r = *(const float4*)(P - 32); wd += sum4(r);
            r = *(const float4*)(P - 36); wd += sum4(r);
            r = *(const float4*)(P - 40); wd += sum4(r);
        }
        // --- s50: q-vectors consumed, reloaded later for lags ---
        float s50;
        {
            float4 q52 = *(const float4*)(P - 52);
            float4 q48 = *(const float4*)(P - 48);
            float4 q44 = *(const float4*)(P - 44);
            s50 = q52.z + q52.w + sum4(q48) + sum4(q44) + wd + w;
        }
        // --- V-init: reload r one vector at a time (peak 6 vectors live) ---
        float V = 0.f;
        {
            float wr = wd;
            float4 r;
            #define VSTEP(xv, xo) { wr += (xv) - (xo); float ma = wr * 0.05f; \
                                    float tt = (xv) - ma; V = fmaf(tt, tt, V); }
            r = *(const float4*)(P - 40);
            VSTEP(h5.x, r.x) VSTEP(h5.y, r.y) VSTEP(h5.z, r.z) VSTEP(h5.w, r.w)
            r = *(const float4*)(P - 36);
            VSTEP(h4.x, r.x) VSTEP(h4.y, r.y) VSTEP(h4.z, r.z) VSTEP(h4.w, r.w)
            r = *(const float4*)(P - 32);
            VSTEP(h3.x, r.x) VSTEP(h3.y, r.y) VSTEP(h3.z, r.z) VSTEP(h3.w, r.w)
            r = *(const float4*)(P - 28);
            VSTEP(h2.x, r.x) VSTEP(h2.y, r.y) VSTEP(h2.z, r.z) VSTEP(h2.w, r.w)
            r = *(const float4*)(P - 24);
            VSTEP(h1.x, r.x) VSTEP(h1.y, r.y) VSTEP(h1.z, r.z) VSTEP(h1.w, r.w)
            #undef VSTEP
        }

        float xs[4] = {xt.x, xt.y, xt.z, xt.w};
        float b0[4], b1[4];

        // --- MA5 (s5 retires) ---
        {
            float lag[4] = {h2.w, h1.x, h1.y, h1.z};
            #pragma unroll
            for (int k = 0; k < 4; ++k) {
                s5 += xs[k] - lag[k];
                b0[k] = s5 * 0.2f;
                b1[k] = __fdividef(xs[k], b0[k] + FEPS);
            }
            __stcs((float4*)(ob + 0 * BT), make_float4(b0[0], b0[1], b0[2], b0[3]));
            __stcs((float4*)(ob + 1 * BT), make_float4(b1[0], b1[1], b1[2], b1[3]));
        }
        // --- MA10 (s10 retires) ---
        {
            float lag[4] = {h3.z, h3.w, h2.x, h2.y};
            #pragma unroll
            for (int k = 0; k < 4; ++k) {
                s10 += xs[k] - lag[k];
                b0[k] = s10 * 0.1f;
                b1[k] = __fdividef(xs[k], b0[k] + FEPS);
            }
            __stcs((float4*)(ob + 2 * BT), make_float4(b0[0], b0[1], b0[2], b0[3]));
            __stcs((float4*)(ob + 3 * BT), make_float4(b1[0], b1[1], b1[2], b1[3]));
        }
        // --- MA50 (q reloaded, s50 retires) ---
        {
            float4 q52 = *(const float4*)(P - 52);
            float4 q48 = *(const float4*)(P - 48);
            float lag[4] = {q52.z, q52.w, q48.x, q48.y};
            #pragma unroll
            for (int k = 0; k < 4; ++k) {
                s50 += xs[k] - lag[k];
                b0[k] = s50 * 0.02f;
                b1[k] = __fdividef(xs[k], b0[k] + FEPS);
            }
            __stcs((float4*)(ob + 6 * BT), make_float4(b0[0], b0[1], b0[2], b0[3]));
            __stcs((float4*)(ob + 7 * BT), make_float4(b1[0], b1[1], b1[2], b1[3]));
        }
        // --- RSI/ATR (gs, ls, xprev, xm15 retire) ---
        {
            float a14[4] = {h4.z, h4.w, h3.x, h3.y};
            #pragma unroll
            for (int k = 0; k < 4; ++k) {
                float d = xs[k] - xprev;
                gs += fmaxf(d, 0.f);
                ls += fmaxf(-d, 0.f);
                float dl = a14[k] - xm15;
                gs -= fmaxf(dl, 0.f);
                ls -= fmaxf(-dl, 0.f);
                xm15 = a14[k]; xprev = xs[k];
                b0[k] = 100.f * __fdividef(gs, gs + ls + 14.f * FEPS);
                b1[k] = (gs + ls) * (1.f / 14.f);
            }
            __stcs((float4*)(ob + 8  * BT), make_float4(b0[0], b0[1], b0[2], b0[3]));
            __stcs((float4*)(ob + 16 * BT), make_float4(b1[0], b1[1], b1[2], b1[3]));
        }
        // --- MA20 (w retires; ma20 persists for BB) ---
        float ma20[4];
        {
            #pragma unroll
            for (int k = 0; k < 4; ++k) {
                float a20k = (k == 0) ? h5.x : (k == 1) ? h5.y : (k == 2) ? h5.z : h5.w;
                w += xs[k] - a20k;
                ma20[k] = w * 0.05f;
                b1[k] = __fdividef(xs[k], ma20[k] + FEPS);
            }
            __stcs((float4*)(ob + 4 * BT), make_float4(ma20[0], ma20[1], ma20[2], ma20[3]));
            __stcs((float4*)(ob + 5 * BT), make_float4(b1[0], b1[1], b1[2], b1[3]));
        }
        // --- BB (a40 reloaded) ---
        {
            float4 a40 = *(const float4*)(P - 40);
            float a20[4] = {h5.x, h5.y, h5.z, h5.w};
            float a40a[4] = {a40.x, a40.y, a40.z, a40.w};
            float b2[4];
            #pragma unroll
            for (int k = 0; k < 4; ++k) {
                float xo = a20[k];
                wd += xo - a40a[k];
                float mad = wd * 0.05f;
                float tn = xs[k] - ma20[k];
                float to = xo - mad;
                V += tn * tn - to * to;
                float var = fmaxf(V, 0.f) * 0.05f;
                float sd  = sqrtf(var + FEPS);
                float bu = ma20[k] + 2.f * sd;
                float bl = ma20[k] - 2.f * sd;
                b0[k] = bu; b1[k] = bl;
                b2[k] = __fdividef(xs[k] - bl, bu - bl + FEPS);
            }
            __stcs((float4*)(ob + 12 * BT), make_float4(b0[0], b0[1], b0[2], b0[3]));
            __stcs((float4*)(ob + 13 * BT), make_float4(ma20[0], ma20[1], ma20[2], ma20[3]));
            __stcs((float4*)(ob + 14 * BT), make_float4(b1[0], b1[1], b1[2], b1[3]));
            __stcs((float4*)(ob + 15 * BT), make_float4(b2[0], b2[1], b2[2], b2[3]));
        }
    } else {
        // slow path: first 13 threads of seg-0 blocks (exact clamped reference)
        #pragma unroll 1
        for (int k = 0; k < WCH; ++k) {
            int t = gbase + k;
            float xt = G[t];
            float s5 = 0.f, s10 = 0.f, s20 = 0.f, s50 = 0.f;
            #pragma unroll 1
            for (int i = 0; i < 50; ++i) {
                float v = G[max(t - i, 0)];
                s50 += v;
                if (i < 20) s20 += v;
                if (i < 10) s10 += v;
                if (i < 5)  s5  += v;
            }
            float ma5 = s5 * 0.2f, ma10 = s10 * 0.1f, ma20 = s20 * 0.05f, ma50 = s50 * 0.02f;
            ob[0 * BT + k] = ma5;  ob[1 * BT + k] = __fdividef(xt, ma5  + FEPS);
            ob[2 * BT + k] = ma10; ob[3 * BT + k] = __fdividef(xt, ma10 + FEPS);
            ob[4 * BT + k] = ma20; ob[5 * BT + k] = __fdividef(xt, ma20 + FEPS);
            ob[6 * BT + k] = ma50; ob[7 * BT + k] = __fdividef(xt, ma50 + FEPS);
            float gs = 0.f, ls = 0.f;
            #pragma unroll 1
            for (int j = t - 13; j <= t; ++j) {
                float d = G[max(j, 0)] - G[max(j - 1, 0)];
                gs += fmaxf(d, 0.f);
                ls += fmaxf(-d, 0.f);
            }
            ob[8  * BT + k] = 100.f * __fdividef(gs, gs + ls + 14.f * FEPS);
            ob[16 * BT + k] = (gs + ls) * (1.f / 14.f);
            float sj = 0.f;
            #pragma unroll 1
            for (int i = 0; i < 20; ++i) sj += G[max(t - 20 - i, 0)];
            float V = 0.f;
            #pragma unroll 1
            for (int j = t - 19; j <= t; ++j) {
                sj += G[max(j, 0)] - G[max(j - 20, 0)];
                float ma = sj * 0.05f;
                float dv = G[max(j, 0)] - ma;
                V = fmaf(dv, dv, V);
            }
            float var = V * 0.05f;
            float sd = sqrtf(var + FEPS);
            float bu = ma20 + 2.f * sd, bl = ma20 - 2.f * sd;
            ob[12 * BT + k] = bu;
            ob[13 * BT + k] = ma20;
            ob[14 * BT + k] = bl;
            ob[15 * BT + k] = __fdividef(xt - bl, bu - bl + FEPS);
        }
    }
}

// ===== fused dispatch (r15): 1024 ema interleaved in first 4096 bids,
//       last 1024 bids pure win; now at 5 CTAs/SM =====
extern "C" __global__ void __launch_bounds__(NTH, 5)
feat_fused(const float* __restrict__ gclose, float* __restrict__ gout, size_t BT)
{
    const int bid = blockIdx.x;
    if (bid < 4096) {
        if ((bid & 3) == 0) ema_body(bid >> 2, gclose, gout, BT);            // 1024 ema
        else                win_body(bid - (bid >> 2) - 1, gclose, gout, BT); // 3072 win
    } else {
        win_body(bid - 1024, gclose, gout, BT);                               // 1024 win
    }
}

extern "C" void kernel_launch(void* const* d_in, const int* in_sizes, int n_in,
                              void* d_out, int out_size)
{
    const float* close = (const float*)d_in[0];
    float* out = (float*)d_out;
    int B = in_sizes[0] / TT;                 // 512
    size_t BT = (size_t)B * TT;
    feat_fused<<<B * 10, NTH>>>(close, out, BT);   // 1024 ema + 4096 win
}

// round 17
// speedup vs baseline: 1.0937x; 1.0937x over previous
#include <cuda_runtime.h>

#define TT    8192
#define NTH   256
#define NW    (NTH/32)
#define FEPS  1e-8f

// ---- ema geometry: SEG=4096, smem-free, aligned 16-chunks ----
#define SEG1  4096
#define ECH   16

// ---- win geometry ----
#define WSEG  1024
#define WCH   4

__device__ __forceinline__ float sum4(float4 v){ return (v.x + v.y) + (v.z + v.w); }

// ======================= ema body: features 9,10,11 — registers only =======================
__device__ void ema_body(int blk, const float* __restrict__ gclose,
                         float* __restrict__ gout, size_t BT)
{
    __shared__ float swp[3 * NW];

    const int row  = blk >> 1;
    const int seg  = blk & 1;
    const int tid  = threadIdx.x;
    const int lane = tid & 31;
    const int wid  = tid >> 5;
    const float* x = gclose + (size_t)row * TT;
    const int basem = seg * SEG1;
    const int i0 = basem + ECH * tid;

    const float aF = 2.0f / 13.0f, omF = 1.0f - aF;
    const float aS = 2.0f / 27.0f, omS = 1.0f - aS;
    const float aG = 0.2f,         omG = 0.8f;

    // ---- load own chunk into registers (4 x LDG.128) ----
    float v[ECH];
    {
        const float4* p4 = (const float4*)(x + i0);
        #pragma unroll
        for (int j = 0; j < 4; ++j) {
            float4 t4 = p4[j];
            v[4*j] = t4.x; v[4*j+1] = t4.y; v[4*j+2] = t4.z; v[4*j+3] = t4.w;
        }
    }

    // ---- seg1 halo: warp 0 pre-scans [basem-256, basem) from global ----
    float hF = 0.f, hS = 0.f, h9 = 0.f;
    if (seg == 1 && wid == 0) {
        float cF = 1.f, dF = 0.f, cS = 1.f, dS = 0.f;
        float cG = 1.f, p = 0.f, q = 0.f, d9 = 0.f;
        const float4* hp = (const float4*)(x + basem - 256 + 8 * lane);
        #pragma unroll
        for (int j = 0; j < 2; ++j) {
            float4 t4 = hp[j];
            float hv[4] = {t4.x, t4.y, t4.z, t4.w};
            #pragma unroll
            for (int k = 0; k < 4; ++k) {
                float vv = hv[k];
                dF = fmaf(aF, vv, omF * dF); cF *= omF;
                dS = fmaf(aS, vv, omS * dS); cS *= omS;
                d9 = fmaf(omG, d9, aG * (dF - dS));
                p  = fmaf(omG, p,  aG * cF);
                q  = fmaf(omG, q, -aG * cS);
                cG *= omG;
            }
        }
        #pragma unroll
        for (int off = 1; off < 32; off <<= 1) {
            float pcF = __shfl_up_sync(0xffffffffu, cF, off);
            float pdF = __shfl_up_sync(0xffffffffu, dF, off);
            float pcS = __shfl_up_sync(0xffffffffu, cS, off);
            float pdS = __shfl_up_sync(0xffffffffu, dS, off);
            float pcG = __shfl_up_sync(0xffffffffu, cG, off);
            float pp  = __shfl_up_sync(0xffffffffu, p,  off);
            float pq  = __shfl_up_sync(0xffffffffu, q,  off);
            float pd9 = __shfl_up_sync(0xffffffffu, d9, off);
            if (lane >= off) {
                float nd9 = fmaf(p, pdF, fmaf(q, pdS, fmaf(cG, pd9, d9)));
                float np  = fmaf(p, pcF, cG * pp);
                float nq  = fmaf(q, pcS, cG * pq);
                dF = fmaf(pdF, cF, dF); cF *= pcF;
                dS = fmaf(pdS, cS, dS); cS *= pcS;
                cG *= pcG;
                p = np; q = nq; d9 = nd9;
            }
        }
        // halo spans 256 elems: incoming-state decay ~1e-17 -> aggregate d's are the state
        hF = __shfl_sync(0xffffffffu, dF, 31);
        hS = __shfl_sync(0xffffffffu, dS, 31);
        h9 = __shfl_sync(0xffffffffu, d9, 31);
    }

    // ---- local merged transform over v[16] ----
    float cF, dF, cS, dS, cG, p, q, d9;
    const bool first = (tid == 0 && seg == 0);
    if (first) {
        // exact reference init at t=0
        float yF = v[0], yS = v[0], y9 = 0.f;
        #pragma unroll
        for (int k = 1; k < ECH; ++k) {
            float vv = v[k];
            yF = fmaf(aF, vv, omF * yF);
            yS = fmaf(aS, vv, omS * yS);
            float m = yF - yS;
            y9 = fmaf(aG, m, omG * y9);
        }
        cF = 0.f; dF = yF; cS = 0.f; dS = yS; cG = 0.f; p = 0.f; q = 0.f; d9 = y9;
    } else {
        cF = 1.f; dF = 0.f; cS = 1.f; dS = 0.f; cG = 1.f; p = 0.f; q = 0.f; d9 = 0.f;
        #pragma unroll
        for (int k = 0; k < ECH; ++k) {
            float vv = v[k];
            dF = fmaf(aF, vv, omF * dF); cF *= omF;
            dS = fmaf(aS, vv, omS * dS); cS *= omS;
            d9 = fmaf(omG, d9, aG * (dF - dS));
            p  = fmaf(omG, p,  aG * cF);
            q  = fmaf(omG, q, -aG * cS);
            cG *= omG;
        }
    }

    // ---- 8-state affine warp scan ----
    #pragma unroll
    for (int off = 1; off < 32; off <<= 1) {
        float pcF = __shfl_up_sync(0xffffffffu, cF, off);
        float pdF = __shfl_up_sync(0xffffffffu, dF, off);
        float pcS = __shfl_up_sync(0xffffffffu, cS, off);
        float pdS = __shfl_up_sync(0xffffffffu, dS, off);
        float pcG = __shfl_up_sync(0xffffffffu, cG, off);
        float pp  = __shfl_up_sync(0xffffffffu, p,  off);
        float pq  = __shfl_up_sync(0xffffffffu, q,  off);
        float pd9 = __shfl_up_sync(0xffffffffu, d9, off);
        if (lane >= off) {
            float nd9 = fmaf(p, pdF, fmaf(q, pdS, fmaf(cG, pd9, d9)));
            float np  = fmaf(p, pcF, cG * pp);
            float nq  = fmaf(q, pcS, cG * pq);
            dF = fmaf(pdF, cF, dF); cF *= pcF;
            dS = fmaf(pdS, cS, dS); cS *= pcS;
            cG *= pcG;
            p = np; q = nq; d9 = nd9;
        }
    }
    if (lane == 31) { swp[wid] = dF; swp[NW + wid] = dS; swp[2 * NW + wid] = d9; }
    float udF = __shfl_up_sync(0xffffffffu, dF, 1);
    float ucF = __shfl_up_sync(0xffffffffu, cF, 1);
    float udS = __shfl_up_sync(0xffffffffu, dS, 1);
    float ucS = __shfl_up_sync(0xffffffffu, cS, 1);
    float ud9 = __shfl_up_sync(0xffffffffu, d9, 1);
    float up  = __shfl_up_sync(0xffffffffu, p,  1);
    float uq  = __shfl_up_sync(0xffffffffu, q,  1);
    float ucG = __shfl_up_sync(0xffffffffu, cG, 1);
    __syncthreads();
    // per-warp decay om^512 ~ 0 -> previous warp's aggregate suffices
    float bF = (wid > 0) ? swp[wid - 1]          : hF;
    float bS = (wid > 0) ? swp[NW + wid - 1]     : hS;
    float b9 = (wid > 0) ? swp[2 * NW + wid - 1] : h9;

    float yF, yS, y9;
    if (lane == 0) { yF = bF; yS = bS; y9 = b9; }
    else {
        yF = fmaf(ucF, bF, udF);
        yS = fmaf(ucS, bS, udS);
        y9 = fmaf(up, bF, fmaf(uq, bS, fmaf(ucG, b9, ud9)));
    }

    // ---- emit macd(9), signal(10), hist(11) from registers ----
    {
        float* ob  = gout + (size_t)row * TT + i0;
        float* om9 = ob + 9  * BT;
        float* osg = ob + 10 * BT;
        float* oh  = ob + 11 * BT;
        #pragma unroll
        for (int g = 0; g < ECH / 4; ++g) {
            float mb[4], sb[4], hb[4];
            #pragma unroll
            for (int jj = 0; jj < 4; ++jj) {
                float vv = v[g * 4 + jj];
                if (first && g == 0 && jj == 0) {
                    yF = vv; yS = vv; y9 = 0.f;
                } else {
                    yF = fmaf(aF, vv, omF * yF);
                    yS = fmaf(aS, vv, omS * yS);
                    float m = yF - yS;
                    y9 = fmaf(aG, m, omG * y9);
                }
                float m = yF - yS;
                mb[jj] = m; sb[jj] = y9; hb[jj] = m - y9;
            }
            __stcs((float4*)(om9 + g * 4), make_float4(mb[0], mb[1], mb[2], mb[3]));
            __stcs((float4*)(osg + g * 4), make_float4(sb[0], sb[1], sb[2], sb[3]));
            __stcs((float4*)(oh  + g * 4), make_float4(hb[0], hb[1], hb[2], hb[3]));
        }
    }
}

// ======== win body: features 0-8, 12-16 — CH=4 (r15 proven, 63 regs) ========
__device__ void win_body(int blk, const float* __restrict__ gclose,
                         float* __restrict__ gout, size_t BT)
{
    const int row = blk >> 3;
    const int seg = blk & 7;
    const int tid = threadIdx.x;
    const float* G = gclose + (size_t)row * TT;
    const int gbase = seg * WSEG + WCH * tid;
    float* ob = gout + (size_t)row * TT + gbase;

    if (gbase >= 52) {
        const float* P = G + gbase;

        float s50q, a50[4];
        {
            float4 q52 = *(const float4*)(P - 52);
            float4 q48 = *(const float4*)(P - 48);
            float4 q44 = *(const float4*)(P - 44);
            a50[0] = q52.z; a50[1] = q52.w; a50[2] = q48.x; a50[3] = q48.y;
            s50q = q52.z + q52.w + sum4(q48) + sum4(q44);
        }

        float4 r24 = *(const float4*)(P - 24);
        float4 r28 = *(const float4*)(P - 28);
        float4 r32 = *(const float4*)(P - 32);
        float4 r36 = *(const float4*)(P - 36);
        float4 r40 = *(const float4*)(P - 40);
        float4 h1  = *(const float4*)(P - 4);
        float4 h2  = *(const float4*)(P - 8);
        float4 h3  = *(const float4*)(P - 12);
        float4 h4  = *(const float4*)(P - 16);
        float4 h5  = *(const float4*)(P - 20);
        float4 xt  = *(const float4*)(P);

        float w  = sum4(h1) + sum4(h2) + sum4(h3) + sum4(h4) + sum4(h5);
        float wd = sum4(r24) + sum4(r28) + sum4(r32) + sum4(r36) + sum4(r40);
        float s50 = s50q + wd + w;
        float s10 = h3.z + h3.w + sum4(h2) + sum4(h1);
        float s5  = h2.w + sum4(h1);
        float gs = 0.f, ls = 0.f;
        {
            #define RSTEP(a, b) { float d = (b) - (a); gs += fmaxf(d, 0.f); ls += fmaxf(-d, 0.f); }
            RSTEP(h4.y, h4.z) RSTEP(h4.z, h4.w) RSTEP(h4.w, h3.x)
            RSTEP(h3.x, h3.y) RSTEP(h3.y, h3.z) RSTEP(h3.z, h3.w)
            RSTEP(h3.w, h2.x) RSTEP(h2.x, h2.y) RSTEP(h2.y, h2.z)
            RSTEP(h2.z, h2.w) RSTEP(h2.w, h1.x) RSTEP(h1.x, h1.y)
            RSTEP(h1.y, h1.z) RSTEP(h1.z, h1.w)
            #undef RSTEP
        }
        float V = 0.f;
        {
            float wr = wd;
            #define VSTEP(xv, xo) { wr += (xv) - (xo); float ma = wr * 0.05f; \
                                    float tt = (xv) - ma; V = fmaf(tt, tt, V); }
            VSTEP(h5.x, r40.x) VSTEP(h5.y, r40.y) VSTEP(h5.z, r40.z) VSTEP(h5.w, r40.w)
            VSTEP(h4.x, r36.x) VSTEP(h4.y, r36.y) VSTEP(h4.z, r36.z) VSTEP(h4.w, r36.w)
            VSTEP(h3.x, r32.x) VSTEP(h3.y, r32.y) VSTEP(h3.z, r32.z) VSTEP(h3.w, r32.w)
            VSTEP(h2.x, r28.x) VSTEP(h2.y, r28.y) VSTEP(h2.z, r28.z) VSTEP(h2.w, r28.w)
            VSTEP(h1.x, r24.x) VSTEP(h1.y, r24.y) VSTEP(h1.z, r24.z) VSTEP(h1.w, r24.w)
            #undef VSTEP
        }
        float xprev = h1.w;
        float xm15  = h4.y;

        float xs[4]  = {xt.x, xt.y, xt.z, xt.w};
        float a5[4]  = {h2.w, h1.x, h1.y, h1.z};
        float a10[4] = {h3.z, h3.w, h2.x, h2.y};
        float a14[4] = {h4.z, h4.w, h3.x, h3.y};
        float a20[4] = {h5.x, h5.y, h5.z, h5.w};
        float a40[4] = {r40.x, r40.y, r40.z, r40.w};

        float b0[4], b1[4], ma20[4];

        #pragma unroll
        for (int k = 0; k < 4; ++k) {
            s5 += xs[k] - a5[k];
            b0[k] = s5 * 0.2f;
            b1[k] = __fdividef(xs[k], b0[k] + FEPS);
        }
        __stcs((float4*)(ob + 0 * BT), make_float4(b0[0], b0[1], b0[2], b0[3]));
        __stcs((float4*)(ob + 1 * BT), make_float4(b1[0], b1[1], b1[2], b1[3]));
        #pragma unroll
        for (int k = 0; k < 4; ++k) {
            s10 += xs[k] - a10[k];
            b0[k] = s10 * 0.1f;
            b1[k] = __fdividef(xs[k], b0[k] + FEPS);
        }
        __stcs((float4*)(ob + 2 * BT), make_float4(b0[0], b0[1], b0[2], b0[3]));
        __stcs((float4*)(ob + 3 * BT), make_float4(b1[0], b1[1], b1[2], b1[3]));
        #pragma unroll
        for (int k = 0; k < 4; ++k) {
            w += xs[k] - a20[k];
            ma20[k] = w * 0.05f;
            b1[k] = __fdividef(xs[k], ma20[k] + FEPS);
        }
        __stcs((float4*)(ob + 4 * BT), make_float4(ma20[0], ma20[1], ma20[2], ma20[3]));
        __stcs((float4*)(ob + 5 * BT), make_float4(b1[0], b1[1], b1[2], b1[3]));
        #pragma unroll
        for (int k = 0; k < 4; ++k) {
            s50 += xs[k] - a50[k];
            b0[k] = s50 * 0.02f;
            b1[k] = __fdividef(xs[k], b0[k] + FEPS);
        }
        __stcs((float4*)(ob + 6 * BT), make_float4(b0[0], b0[1], b0[2], b0[3]));
        __stcs((float4*)(ob + 7 * BT), make_float4(b1[0], b1[1], b1[2], b1[3]));
        #pragma unroll
        for (int k = 0; k < 4; ++k) {
            float d = xs[k] - xprev;
            gs += fmaxf(d, 0.f);
            ls += fmaxf(-d, 0.f);
            float dl = a14[k] - xm15;
            gs -= fmaxf(dl, 0.f);
            ls -= fmaxf(-dl, 0.f);
            xm15 = a14[k]; xprev = xs[k];
            b0[k] = 100.f * __fdividef(gs, gs + ls + 14.f * FEPS);
            b1[k] = (gs + ls) * (1.f / 14.f);
        }
        __stcs((float4*)(ob + 8  * BT), make_float4(b0[0], b0[1], b0[2], b0[3]));
        __stcs((float4*)(ob + 16 * BT), make_float4(b1[0], b1[1], b1[2], b1[3]));
        float b2[4];
        #pragma unroll
        for (int k = 0; k < 4; ++k) {
            float xo = a20[k];
            wd += xo - a40[k];
            float mad = wd * 0.05f;
            float tn = xs[k] - ma20[k];
            float to = xo - mad;
            V += tn * tn - to * to;
            float var = fmaxf(V, 0.f) * 0.05f;
            float sd  = sqrtf(var + FEPS);
            float bu = ma20[k] + 2.f * sd;
            float bl = ma20[k] - 2.f * sd;
            b0[k] = bu; b1[k] = bl;
            b2[k] = __fdividef(xs[k] - bl, bu - bl + FEPS);
        }
        __stcs((float4*)(ob + 12 * BT), make_float4(b0[0], b0[1], b0[2], b0[3]));
        __stcs((float4*)(ob + 13 * BT), make_float4(ma20[0], ma20[1], ma20[2], ma20[3]));
        __stcs((float4*)(ob + 14 * BT), make_float4(b1[0], b1[1], b1[2], b1[3]));
        __stcs((float4*)(ob + 15 * BT), make_float4(b2[0], b2[1], b2[2], b2[3]));
    } else {
        // slow path: first 13 threads of seg-0 blocks (exact clamped reference)
        #pragma unroll 1
        for (int k = 0; k < WCH; ++k) {
            int t = gbase + k;
            float xt = G[t];
            float s5 = 0.f, s10 = 0.f, s20 = 0.f, s50 = 0.f;
            #pragma unroll 1
            for (int i = 0; i < 50; ++i) {
                float v = G[max(t - i, 0)];
                s50 += v;
                if (i < 20) s20 += v;
                if (i < 10) s10 += v;
                if (i < 5)  s5  += v;
            }
            float ma5 = s5 * 0.2f, ma10 = s10 * 0.1f, ma20 = s20 * 0.05f, ma50 = s50 * 0.02f;
            ob[0 * BT + k] = ma5;  ob[1 * BT + k] = __fdividef(xt, ma5  + FEPS);
            ob[2 * BT + k] = ma10; ob[3 * BT + k] = __fdividef(xt, ma10 + FEPS);
            ob[4 * BT + k] = ma20; ob[5 * BT + k] = __fdividef(xt, ma20 + FEPS);
            ob[6 * BT + k] = ma50; ob[7 * BT + k] = __fdividef(xt, ma50 + FEPS);
            float gs = 0.f, ls = 0.f;
            #pragma unroll 1
            for (int j = t - 13; j <= t; ++j) {
                float d = G[max(j, 0)] - G[max(j - 1, 0)];
                gs += fmaxf(d, 0.f);
                ls += fmaxf(-d, 0.f);
            }
            ob[8  * BT + k] = 100.f * __fdividef(gs, gs + ls + 14.f * FEPS);
            ob[16 * BT + k] = (gs + ls) * (1.f / 14.f);
            float sj = 0.f;
            #pragma unroll 1
            for (int i = 0; i < 20; ++i) sj += G[max(t - 20 - i, 0)];
            float V = 0.f;
            #pragma unroll 1
            for (int j = t - 19; j <= t; ++j) {
                sj += G[max(j, 0)] - G[max(j - 20, 0)];
                float ma = sj * 0.05f;
                float dv = G[max(j, 0)] - ma;
                V = fmaf(dv, dv, V);
            }
            float var = V * 0.05f;
            float sd = sqrtf(var + FEPS);
            float bu = ma20 + 2.f * sd, bl = ma20 - 2.f * sd;
            ob[12 * BT + k] = bu;
            ob[13 * BT + k] = ma20;
            ob[14 * BT + k] = bl;
            ob[15 * BT + k] = __fdividef(xt - bl, bu - bl + FEPS);
        }
    }
}

// ===== fused dispatch: 1024 ema interleaved in first 4096 bids, last 1024 pure win =====
extern "C" __global__ void __launch_bounds__(NTH, 4)
feat_fused(const float* __restrict__ gclose, float* __restrict__ gout, size_t BT)
{
    const int bid = blockIdx.x;
    if (bid < 4096) {
        if ((bid & 3) == 0) ema_body(bid >> 2, gclose, gout, BT);            // 1024 ema
        else                win_body(bid - (bid >> 2) - 1, gclose, gout, BT); // 3072 win
    } else {
        win_body(bid - 1024, gclose, gout, BT);                               // 1024 win
    }
}

extern "C" void kernel_launch(void* const* d_in, const int* in_sizes, int n_in,
                              void* d_out, int out_size)
{
    const float* close = (const float*)d_in[0];
    float* out = (float*)d_out;
    int B = in_sizes[0] / TT;                 // 512
    size_t BT = (size_t)B * TT;
    feat_fused<<<B * 10, NTH>>>(close, out, BT);   // 1024 ema + 4096 win
}